// round 11
// baseline (speedup 1.0000x reference)
#include <cuda_runtime.h>

// Soft-DTW, gamma = 0.01, p = 2, B = 64, M = N = 512.
// One CTA per batch; 256 threads; thread jj owns columns colA=2jj, colB=2jj+1.
// At global step s = local t + 64w, thread jj computes:
//   A = (iiA = t - 2*lane, colA), B = (iiA - 1, colB)
//   B deps all-register; A deps via shfl (lane>0) / mailbox (lane 0).
// Cross-warp mailbox: write-once 512 slots {value, tag=row}, one STS.64 each.
// Consumer keeps slack DELTA: it verifies the tag of slot t+1+DELTA (prefetched
// one iteration early -> setp on a ready register, off the critical chain) and
// reads the value of slot t+1 unconditionally (st.volatile program order from
// the producer guarantees visibility). After any spin, slack resets to DELTA.

#define BIG   1e30f
#define KEXP  144.26950408889634f    // 100 * log2(e)
#define GLN2  0.006931471805599453f  // 0.01 * ln(2)
#define DELTA 12

__device__ __forceinline__ float ex2f_(float v) {
    float r; asm("ex2.approx.ftz.f32 %0, %1;" : "=f"(r) : "f"(v)); return r;
}
__device__ __forceinline__ float lg2f_(float v) {
    float r; asm("lg2.approx.ftz.f32 %0, %1;" : "=f"(r) : "f"(v)); return r;
}

// softmin3 = m - gamma*ln(1 + e^{(m-v1)/g} + e^{(m-v2)/g})  (proven numerics)
__device__ __forceinline__ float softmin3(float dg, float up, float lf) {
    float t1 = fminf(dg, up);
    float t2 = fmaxf(dg, up);
    float m  = fminf(t1, lf);
    float u  = fmaxf(t1, lf);
    float mk = m * KEXP;
    float a1 = fmaf(-KEXP, t2, mk);
    float a2 = fmaf(-KEXP, u,  mk);
    float ss = 1.0f + ex2f_(a1) + ex2f_(a2);
    return fmaf(-GLN2, lg2f_(ss), m);
}

__device__ __forceinline__ unsigned lds_u32_vol(const void* p) {
    unsigned a = (unsigned)__cvta_generic_to_shared(p); unsigned v;
    asm volatile("ld.volatile.shared.u32 %0, [%1];" : "=r"(v) : "r"(a));
    return v;
}
__device__ __forceinline__ void sts_v2_vol(uint2* p, unsigned vx, unsigned vy) {
    unsigned a = (unsigned)__cvta_generic_to_shared(p);
    asm volatile("st.volatile.shared.v2.u32 [%0], {%1,%2};"
                 :: "r"(a), "r"(vx), "r"(vy) : "memory");
}
// Verify preloaded tag 'cur' == want; rare spin reloads from the slot's tag word.
__device__ __forceinline__ void tag_verify(unsigned cur, unsigned want, const uint2* slot) {
    unsigned a = (unsigned)__cvta_generic_to_shared(&slot->y);
    asm volatile("{\n\t"
        ".reg .pred p;\n\t"
        "setp.eq.u32 p, %0, %1;\n\t"
        "@p bra D%=;\n\t"
        "R%=:\n\t"
        "ld.volatile.shared.u32 %0, [%2];\n\t"
        "setp.ne.u32 p, %0, %1;\n\t"
        "@p bra R%=;\n\t"
        "D%=:\n\t"
        "}" : "+r"(cur) : "r"(want), "r"(a) : "memory");
}

__global__ __launch_bounds__(256, 1)
void softdtw_kernel(const float* __restrict__ x,
                    const float* __restrict__ y,
                    float* __restrict__ out)
{
    __shared__ float yshp_raw[640];  // rows [-64, 576); offset 64; pads zeroed
    __shared__ uint2 bnd[8][512];    // rows 0..6: mailboxes; row 7: dummy (always valid)

    const int b    = blockIdx.x;
    const int jj   = threadIdx.x;          // 0..255
    const int w    = jj >> 5;
    const int lane = jj & 31;
    const int colA = 2 * jj;
    const int colB = colA + 1;
    float* yshp = yshp_raw + 64;

    yshp[colA] = y[b * 512 + colA];
    yshp[colB] = y[b * 512 + colB];
    const float xA = x[b * 512 + colA];
    const float xB = x[b * 512 + colB];
    if (jj < 64) { yshp_raw[jj] = 0.0f; yshp_raw[576 + jj] = 0.0f; }
    {
        uint2* flat = &bnd[0][0];
        for (int t = jj; t < 7 * 512; t += 256) flat[t].y = 0xFFFFFFFFu;
        for (int t = jj; t < 512; t += 256)
            bnd[7][t] = make_uint2(__float_as_uint(BIG), (unsigned)t);
    }
    __syncthreads();                        // the only full barrier

    const uint2* mrow = bnd[(w + 7) & 7];   // w=0 -> dummy row 7; else bnd[w-1]
    uint2*       prow = bnd[w & 7];
    const bool   isPub = (lane == 31) && (w < 7);

    float aPrev  = BIG;                     // A(t-1)
    float aPrev2 = BIG;                     // A(t-2)
    float bPrev  = BIG;                     // B(t-1)
    float nbPrev = (jj == 0) ? 0.0f : BIG;  // neighbor B(t-2); R[-1,-1]=0 seed

    float yA = yshp[-2 * lane];             // ysh[iiA] for t=0 (pad if <0)
    float yB = yshp[-2 * lane - 1];         // ysh[iiA-1]

    // establish initial slack: wait for slot DELTA, then prime value/tag pipeline
    {
        unsigned cur = lds_u32_vol(&mrow[DELTA].y);
        tag_verify(cur, (unsigned)DELTA, &mrow[DELTA]);
    }
    float    preVal = __uint_as_float(lds_u32_vol(&mrow[0].x));
    unsigned tagPre = lds_u32_vol(&mrow[(1 + DELTA < 512) ? 1 + DELTA : 511].y);

    // ---- phase A: t = 0..511 (mailbox active) ----
    #pragma unroll 4
    for (int t = 0; t < 512; ++t) {
        const int iiA  = t - 2 * lane;
        const int rowB = iiA - 1;

        float nbCur = __shfl_up_sync(0xffffffffu, bPrev, 1);
        if (lane == 0) nbCur = preVal;

        // B cell (register-only deps)
        float dB = xB - yB;
        float rB = fmaf(dB, dB, softmin3(aPrev2, bPrev, aPrev));
        rB = ((unsigned)rowB < 512u) ? rB : BIG;

        // publish ASAP to feed downstream warp
        if (isPub && (unsigned)rowB < 512u)
            sts_v2_vol(&prow[rowB], __float_as_uint(rB), (unsigned)rowB);

        // A cell
        float dA = xA - yA;
        float rA = fmaf(dA, dA, softmin3(nbPrev, aPrev, nbCur));
        rA = ((unsigned)iiA < 512u) ? rA : BIG;

        // rotate state
        aPrev2 = aPrev;  aPrev = rA;  bPrev = rB;  nbPrev = nbCur;
        yB = yA;
        yA = yshp[iiA + 1];

        // mailbox pipeline for next iteration (all off the register chain):
        // verify slack-ahead tag (setp on ready reg), load value t+1, prefetch next tag
        int want = t + 1 + DELTA; want = (want < 512) ? want : 511;
        tag_verify(tagPre, (unsigned)want, &mrow[want]);
        int vi = (t + 1 < 512) ? t + 1 : 511;
        preVal = __uint_as_float(lds_u32_vol(&mrow[vi].x));
        int nt = t + 2 + DELTA; nt = (nt < 512) ? nt : 511;
        tagPre = lds_u32_vol(&mrow[nt].y);
    }

    // ---- phase B: t = 512..574 (lane 0 inactive; no mailbox) ----
    #pragma unroll 4
    for (int t = 512; t <= 574; ++t) {
        const int iiA  = t - 2 * lane;
        const int rowB = iiA - 1;

        float nbCur = __shfl_up_sync(0xffffffffu, bPrev, 1);
        if (lane == 0) nbCur = BIG;

        float dB = xB - yB;
        float rB = fmaf(dB, dB, softmin3(aPrev2, bPrev, aPrev));
        rB = ((unsigned)rowB < 512u) ? rB : BIG;

        if (isPub && (unsigned)rowB < 512u)
            sts_v2_vol(&prow[rowB], __float_as_uint(rB), (unsigned)rowB);

        float dA = xA - yA;
        float rA = fmaf(dA, dA, softmin3(nbPrev, aPrev, nbCur));
        rA = ((unsigned)iiA < 512u) ? rA : BIG;

        aPrev2 = aPrev;  aPrev = rA;  bPrev = rB;  nbPrev = nbCur;
        yB = yA;
        yA = yshp[iiA + 1];
    }

    if (jj == 255) out[b] = bPrev;          // B at global step 1022 -> R[511,511]
}

extern "C" void kernel_launch(void* const* d_in, const int* in_sizes, int n_in,
                              void* d_out, int out_size)
{
    const float* x = (const float*)d_in[0];
    const float* y = (const float*)d_in[1];
    float* out = (float*)d_out;
    softdtw_kernel<<<64, 256>>>(x, y, out);
}